// round 1
// baseline (speedup 1.0000x reference)
#include <cuda_runtime.h>

#define N_NODES 200000
#define N_EDGES 6400000
#define IN_DIM  1433
#define HID     16
#define OUTD    7
#define OUTP    8

// -------- scratch (device globals; no runtime allocation allowed) --------
__device__ float g_XW1[N_NODES * HID];          // 12.8 MB  X @ W1
__device__ float g_H  [N_NODES * HID];          // 12.8 MB  L @ (X W1)   (atomic target)
__device__ float g_HW2[N_NODES * OUTP];         //  6.4 MB  relu(H+b1) @ W2, padded to 8
__device__ float g_OUT8[N_NODES * OUTP];        //  6.4 MB  L @ HW2      (atomic target)

// vectorized global float reduction (sm_90+): 4 adds in one RED op
__device__ __forceinline__ void red_add_v4(float* addr, float4 p) {
    asm volatile("red.global.add.v4.f32 [%0], {%1,%2,%3,%4};"
                 :: "l"(addr), "f"(p.x), "f"(p.y), "f"(p.z), "f"(p.w)
                 : "memory");
}

// -------- 0: zero the two atomic targets --------
__global__ void zero_kernel() {
    const int nH = N_NODES * HID / 4;    // in float4
    const int nO = N_NODES * OUTP / 4;
    float4 z = make_float4(0.f, 0.f, 0.f, 0.f);
    int stride = gridDim.x * blockDim.x;
    for (int i = blockIdx.x * blockDim.x + threadIdx.x; i < nH + nO; i += stride) {
        if (i < nH) ((float4*)g_H)[i] = z;
        else        ((float4*)g_OUT8)[i - nH] = z;
    }
}

// -------- 1: GEMM1  g_XW1 = X @ W1   (200000 x 1433 x 16) --------
// 128 threads, 256 rows/block, 2 rows/thread, 32 fp32 accumulators.
// W1 chunk is read as warp-uniform float4 LDS broadcasts -> LDS traffic tiny.
__global__ void __launch_bounds__(128) gemm1_kernel(const float* __restrict__ X,
                                                    const float* __restrict__ W1) {
    __shared__ float As[256][33];   // +1 pad: lane stride 33 -> conflict-free
    __shared__ float Ws[32][16];    // rows are 64B -> float4-aligned

    const int t    = threadIdx.x;
    const int row0 = blockIdx.x * 256;

    float acc0[16], acc1[16];
#pragma unroll
    for (int j = 0; j < 16; j++) { acc0[j] = 0.f; acc1[j] = 0.f; }

    for (int kc = 0; kc < IN_DIM; kc += 32) {
        // stage W1 chunk: 32x16 = 512 floats
#pragma unroll
        for (int s = 0; s < 4; s++) {
            int flat = t + 128 * s;
            int k = flat >> 4, j = flat & 15;
            Ws[k][j] = (kc + k < IN_DIM) ? W1[(kc + k) * HID + j] : 0.f;
        }
        // stage A tile: 256x32 floats, coalesced (consecutive t -> consecutive k)
#pragma unroll
        for (int s = 0; s < 64; s++) {
            int flat = t + 128 * s;
            int r = flat >> 5, k = flat & 31;
            int gr = row0 + r, gk = kc + k;
            As[r][k] = (gr < N_NODES && gk < IN_DIM)
                         ? X[(long)gr * IN_DIM + gk] : 0.f;
        }
        __syncthreads();

#pragma unroll 4
        for (int k = 0; k < 32; k++) {
            const float4* w4 = (const float4*)&Ws[k][0];
            float4 wa = w4[0], wb = w4[1], wc = w4[2], wd = w4[3];
            float w[16];
            *(float4*)&w[0]  = wa; *(float4*)&w[4]  = wb;
            *(float4*)&w[8]  = wc; *(float4*)&w[12] = wd;
            float a0 = As[t][k];
            float a1 = As[t + 128][k];
#pragma unroll
            for (int j = 0; j < 16; j++) {
                acc0[j] = fmaf(a0, w[j], acc0[j]);
                acc1[j] = fmaf(a1, w[j], acc1[j]);
            }
        }
        __syncthreads();
    }

    int r0 = row0 + t, r1 = row0 + t + 128;
    if (r0 < N_NODES) {
        float4* d = (float4*)&g_XW1[r0 * HID];
        d[0] = *(float4*)&acc0[0];  d[1] = *(float4*)&acc0[4];
        d[2] = *(float4*)&acc0[8];  d[3] = *(float4*)&acc0[12];
    }
    if (r1 < N_NODES) {
        float4* d = (float4*)&g_XW1[r1 * HID];
        d[0] = *(float4*)&acc1[0];  d[1] = *(float4*)&acc1[4];
        d[2] = *(float4*)&acc1[8];  d[3] = *(float4*)&acc1[12];
    }
}

// -------- 2: SPMM1  g_H[row] += val * g_XW1[col]  (16 floats/edge) --------
__global__ void __launch_bounds__(256) spmm1_kernel(const int*   __restrict__ erow,
                                                    const int*   __restrict__ ecol,
                                                    const float* __restrict__ evals) {
    int e = blockIdx.x * 256 + threadIdx.x;
    if (e >= N_EDGES) return;
    int r = erow[e], c = ecol[e];
    float v = evals[e];
    const float4* s = (const float4*)&g_XW1[c * HID];
    float4 p0 = s[0], p1 = s[1], p2 = s[2], p3 = s[3];
    p0.x *= v; p0.y *= v; p0.z *= v; p0.w *= v;
    p1.x *= v; p1.y *= v; p1.z *= v; p1.w *= v;
    p2.x *= v; p2.y *= v; p2.z *= v; p2.w *= v;
    p3.x *= v; p3.y *= v; p3.z *= v; p3.w *= v;
    float* dst = &g_H[r * HID];
    red_add_v4(dst + 0,  p0);
    red_add_v4(dst + 4,  p1);
    red_add_v4(dst + 8,  p2);
    red_add_v4(dst + 12, p3);
}

// -------- 3: GEMM2  g_HW2 = relu(g_H + b1) @ W2, padded to 8 cols --------
__global__ void __launch_bounds__(256) gemm2_kernel(const float* __restrict__ b1,
                                                    const float* __restrict__ W2) {
    __shared__ float sW2[HID * OUTD];
    __shared__ float sb1[HID];
    int t = threadIdx.x;
    if (t < HID * OUTD) sW2[t] = W2[t];
    if (t < HID)        sb1[t] = b1[t];
    __syncthreads();

    int i = blockIdx.x * 256 + t;
    if (i >= N_NODES) return;

    const float4* hp = (const float4*)&g_H[i * HID];
    float h[16];
    *(float4*)&h[0]  = hp[0]; *(float4*)&h[4]  = hp[1];
    *(float4*)&h[8]  = hp[2]; *(float4*)&h[12] = hp[3];
#pragma unroll
    for (int j = 0; j < 16; j++) h[j] = fmaxf(h[j] + sb1[j], 0.f);

    float o[OUTP];
#pragma unroll
    for (int c = 0; c < OUTD; c++) {
        float s = 0.f;
#pragma unroll
        for (int j = 0; j < HID; j++) s = fmaf(h[j], sW2[j * OUTD + c], s);
        o[c] = s;
    }
    o[7] = 0.f;  // pad column stays exactly zero

    float4* d = (float4*)&g_HW2[i * OUTP];
    d[0] = *(float4*)&o[0];
    d[1] = *(float4*)&o[4];
}

// -------- 4: SPMM2  g_OUT8[row] += val * g_HW2[col]  (8 floats/edge) --------
__global__ void __launch_bounds__(256) spmm2_kernel(const int*   __restrict__ erow,
                                                    const int*   __restrict__ ecol,
                                                    const float* __restrict__ evals) {
    int e = blockIdx.x * 256 + threadIdx.x;
    if (e >= N_EDGES) return;
    int r = erow[e], c = ecol[e];
    float v = evals[e];
    const float4* s = (const float4*)&g_HW2[c * OUTP];
    float4 p0 = s[0], p1 = s[1];
    p0.x *= v; p0.y *= v; p0.z *= v; p0.w *= v;
    p1.x *= v; p1.y *= v; p1.z *= v; p1.w *= v;
    float* dst = &g_OUT8[r * OUTP];
    red_add_v4(dst + 0, p0);
    red_add_v4(dst + 4, p1);
}

// -------- 5: finalize  out[i][c] = g_OUT8[i][c] + b2[c] --------
__global__ void __launch_bounds__(256) finalize_kernel(const float* __restrict__ b2,
                                                       float* __restrict__ out) {
    int idx = blockIdx.x * 256 + threadIdx.x;
    if (idx >= N_NODES * OUTD) return;
    int i = idx / OUTD, c = idx - i * OUTD;
    out[idx] = g_OUT8[i * OUTP + c] + b2[c];
}

extern "C" void kernel_launch(void* const* d_in, const int* in_sizes, int n_in,
                              void* d_out, int out_size) {
    const float* feature = (const float*)d_in[0];
    const int*   erow    = (const int*)  d_in[1];
    const int*   ecol    = (const int*)  d_in[2];
    const float* evals   = (const float*)d_in[3];
    const float* W1      = (const float*)d_in[4];
    const float* b1      = (const float*)d_in[5];
    const float* W2      = (const float*)d_in[6];
    const float* b2      = (const float*)d_in[7];
    float* out = (float*)d_out;

    zero_kernel<<<4096, 256>>>();

    int gemm1_blocks = (N_NODES + 255) / 256;              // 782
    gemm1_kernel<<<gemm1_blocks, 128>>>(feature, W1);

    int spmm_blocks = (N_EDGES + 255) / 256;               // 25000
    spmm1_kernel<<<spmm_blocks, 256>>>(erow, ecol, evals);

    int node_blocks = (N_NODES + 255) / 256;
    gemm2_kernel<<<node_blocks, 256>>>(b1, W2);

    spmm2_kernel<<<spmm_blocks, 256>>>(erow, ecol, evals);

    int fin_blocks = (N_NODES * OUTD + 255) / 256;
    finalize_kernel<<<fin_blocks, 256>>>(b2, out);
}